// round 1
// baseline (speedup 1.0000x reference)
#include <cuda_runtime.h>
#include <cstdint>
#include <cstddef>

// ---------------------------------------------------------------------------
// RGCN: 2-layer relational graph conv, mean aggregation, ReLU, final L2 norm.
//   N=100000 nodes, E=1600000 edges, R=2 relations, 128 -> 128 -> 64.
// Strategy: scatter-then-transform (segment_sum is linear, so aggregate raw
// features per (rel,dst) then do one dense GEMM per layer with K = 3*128).
// ---------------------------------------------------------------------------

#define NN   100000
#define NE   1600000
#define NREL 2
#define CIN  128
#define CHID 128
#define COUT 64

// Scratch (static device globals; no allocation allowed).
__device__ __align__(128) float g_agg[(size_t)NREL * NN * CIN];   // 102.4 MB
__device__ __align__(128) float g_h[(size_t)NN * CHID];           // 51.2 MB
__device__ float g_cnt[NREL * NN];
__device__ float g_inv[NREL * NN];
__device__ int   g_is64;

// ---------------------------------------------------------------------------
// Edge dtype detection: jax with x64 disabled silently makes these int32.
// If data is int32, reading edge_type as int64 gives a+b*2^32 with b in {0,1}
// random -> huge values appear with overwhelming probability.
// ---------------------------------------------------------------------------
__global__ void detect_kernel(const void* et) {
    const long long* p = (const long long*)et;
    int ok = 1;
    for (int i = 0; i < 512; i++) {
        long long v = p[i];
        if (v < 0 || v >= NREL) { ok = 0; break; }
    }
    g_is64 = ok;
}

__device__ __forceinline__ long long ld_idx(const void* p, long long i, int is64) {
    if (is64) return ((const long long*)p)[i];
    return (long long)((const int*)p)[i];
}

// ---------------------------------------------------------------------------
__global__ void zero_agg_cnt_kernel() {
    size_t i = (size_t)blockIdx.x * blockDim.x + threadIdx.x;
    const size_t n4 = (size_t)NREL * NN * CIN / 4;
    if (i < n4) ((float4*)g_agg)[i] = make_float4(0.f, 0.f, 0.f, 0.f);
    if (i < (size_t)NREL * NN) g_cnt[i] = 0.f;
}

__global__ void zero_agg_kernel() {
    size_t i = (size_t)blockIdx.x * blockDim.x + threadIdx.x;
    const size_t n4 = (size_t)NREL * NN * CIN / 4;
    if (i < n4) ((float4*)g_agg)[i] = make_float4(0.f, 0.f, 0.f, 0.f);
}

__global__ void count_kernel(const void* ei, const void* et) {
    int e = blockIdx.x * blockDim.x + threadIdx.x;
    if (e >= NE) return;
    int is64 = g_is64;
    int dst = (int)ld_idx(ei, (long long)NE + e, is64);
    int r   = (int)ld_idx(et, e, is64);
    atomicAdd(&g_cnt[r * NN + dst], 1.0f);
}

__global__ void inv_kernel() {
    int i = blockIdx.x * blockDim.x + threadIdx.x;
    if (i < NREL * NN) g_inv[i] = 1.0f / fmaxf(g_cnt[i], 1.0f);
}

// ---------------------------------------------------------------------------
// Scatter: one warp per edge. Lane l handles float4 at channel 4l.
// Gather x[src] (512B, 4 full cache lines), vector-reduce into agg[rel][dst].
// ---------------------------------------------------------------------------
__global__ void scatter_kernel(const float* __restrict__ x, int use_h,
                               const void* __restrict__ ei,
                               const void* __restrict__ et) {
    long long gtid = (long long)blockIdx.x * blockDim.x + threadIdx.x;
    int e    = (int)(gtid >> 5);
    int lane = (int)(gtid & 31);
    if (e >= NE) return;
    int is64 = g_is64;
    int src = (int)ld_idx(ei, e, is64);
    int dst = (int)ld_idx(ei, (long long)NE + e, is64);
    int r   = (int)ld_idx(et, e, is64);

    const float* base = use_h ? g_h : x;
    float4 v = ((const float4*)(base + (size_t)src * CIN))[lane];
    float* a = g_agg + ((size_t)r * NN + dst) * CIN + lane * 4;
    asm volatile("red.global.add.v4.f32 [%0], {%1,%2,%3,%4};"
                 :: "l"(a), "f"(v.x), "f"(v.y), "f"(v.z), "f"(v.w)
                 : "memory");
}

// ---------------------------------------------------------------------------
// Fused combine GEMM:  out = act( [x | agg0*inv0 | agg1*inv1] @
//                                 [Wroot ; Wrel0 ; Wrel1] + bias )
// K = 384 (3 segments of 128). BM=128, BN=64, BK=16, 256 threads, TM=8 TN=4.
// L1: out -> g_h with ReLU.  L2: out -> param (pre-normalization).
// ---------------------------------------------------------------------------
template <int OUTC, bool LAYER1>
__global__ void combine_kernel(const float* __restrict__ Ax,
                               const float* __restrict__ Wroot,
                               const float* __restrict__ Wrel,
                               const float* __restrict__ bias,
                               float* __restrict__ out_param) {
    __shared__ float As[16][128];
    __shared__ float Bs[16][64];

    const float* A0 = LAYER1 ? Ax : g_h;
    float*       out = LAYER1 ? g_h : out_param;

    int tid = threadIdx.x;
    int m0 = blockIdx.x * 128;
    int n0 = blockIdx.y * 64;
    int tn = (tid & 15) * 4;
    int tm = (tid >> 4) * 8;

    float acc[8][4];
#pragma unroll
    for (int i = 0; i < 8; i++)
#pragma unroll
        for (int j = 0; j < 4; j++) acc[i][j] = 0.f;

    for (int kt = 0; kt < 24; kt++) {
        int seg  = kt >> 3;           // 0: root input, 1/2: relation aggs
        int krel = (kt & 7) * 16;     // k offset within the 128-wide segment
        const float* Asrc = (seg == 0) ? A0 : (g_agg + (size_t)(seg - 1) * NN * 128);
        const float* Bsrc = (seg == 0) ? Wroot : (Wrel + (size_t)(seg - 1) * 128 * OUTC);

        // Load A tile (128 rows x 16 k), transposed into As[k][row].
#pragma unroll
        for (int i = 0; i < 2; i++) {
            int idx = tid * 2 + i;        // 0..511
            int ar  = idx >> 2;           // row 0..127
            int ak  = (idx & 3) * 4;      // k4 offset
            int node = m0 + ar;
            float4 v = make_float4(0.f, 0.f, 0.f, 0.f);
            if (node < NN) {
                v = *(const float4*)(Asrc + (size_t)node * 128 + krel + ak);
                if (seg > 0) {
                    float s = g_inv[(seg - 1) * NN + node];
                    v.x *= s; v.y *= s; v.z *= s; v.w *= s;
                }
            }
            As[ak + 0][ar] = v.x;
            As[ak + 1][ar] = v.y;
            As[ak + 2][ar] = v.z;
            As[ak + 3][ar] = v.w;
        }
        // Load B tile (16 k x 64 n).
        {
            int bk = tid >> 4;
            int bn = (tid & 15) * 4;
            float4 v = *(const float4*)(Bsrc + (size_t)(krel + bk) * OUTC + n0 + bn);
            *(float4*)&Bs[bk][bn] = v;
        }
        __syncthreads();

#pragma unroll
        for (int k = 0; k < 16; k++) {
            float4 a0 = *(const float4*)&As[k][tm];
            float4 a1 = *(const float4*)&As[k][tm + 4];
            float4 b0 = *(const float4*)&Bs[k][tn];
            float av[8] = {a0.x, a0.y, a0.z, a0.w, a1.x, a1.y, a1.z, a1.w};
            float bv[4] = {b0.x, b0.y, b0.z, b0.w};
#pragma unroll
            for (int i = 0; i < 8; i++)
#pragma unroll
                for (int j = 0; j < 4; j++) acc[i][j] += av[i] * bv[j];
        }
        __syncthreads();
    }

    float bv[4];
#pragma unroll
    for (int j = 0; j < 4; j++) bv[j] = bias[n0 + tn + j];
#pragma unroll
    for (int i = 0; i < 8; i++) {
        int node = m0 + tm + i;
        if (node < NN) {
            float4 o;
            o.x = acc[i][0] + bv[0];
            o.y = acc[i][1] + bv[1];
            o.z = acc[i][2] + bv[2];
            o.w = acc[i][3] + bv[3];
            if (LAYER1) {
                o.x = fmaxf(o.x, 0.f); o.y = fmaxf(o.y, 0.f);
                o.z = fmaxf(o.z, 0.f); o.w = fmaxf(o.w, 0.f);
            }
            *(float4*)(out + (size_t)node * OUTC + n0 + tn) = o;
        }
    }
}

// ---------------------------------------------------------------------------
// Row L2 normalize: one warp per node, 64 floats = 32 float2.
// ---------------------------------------------------------------------------
__global__ void normalize_kernel(float* __restrict__ out) {
    long long gtid = (long long)blockIdx.x * blockDim.x + threadIdx.x;
    int node = (int)(gtid >> 5);
    int lane = (int)(gtid & 31);
    if (node >= NN) return;
    float2* row = (float2*)(out + (size_t)node * COUT);
    float2 v = row[lane];
    float ss = v.x * v.x + v.y * v.y;
#pragma unroll
    for (int o = 16; o; o >>= 1) ss += __shfl_xor_sync(0xFFFFFFFFu, ss, o);
    float s = 1.0f / fmaxf(sqrtf(ss), 1e-12f);
    v.x *= s; v.y *= s;
    row[lane] = v;
}

// ---------------------------------------------------------------------------
extern "C" void kernel_launch(void* const* d_in, const int* in_sizes, int n_in,
                              void* d_out, int out_size) {
    const float* x       = (const float*)d_in[0];
    const void*  ei      = d_in[1];
    const void*  et      = d_in[2];
    const float* W1_rel  = (const float*)d_in[3];
    const float* W1_root = (const float*)d_in[4];
    const float* b1      = (const float*)d_in[5];
    const float* W2_rel  = (const float*)d_in[6];
    const float* W2_root = (const float*)d_in[7];
    const float* b2      = (const float*)d_in[8];
    float* out = (float*)d_out;

    const int ZERO_BLOCKS = (int)(((size_t)NREL * NN * CIN / 4 + 255) / 256); // 25000
    const int MT = (NN + 127) / 128;                                          // 782

    detect_kernel<<<1, 1>>>(et);
    zero_agg_cnt_kernel<<<ZERO_BLOCKS, 256>>>();
    count_kernel<<<(NE + 255) / 256, 256>>>(ei, et);
    inv_kernel<<<(NREL * NN + 255) / 256, 256>>>();

    // Layer 1
    scatter_kernel<<<NE / 8, 256>>>(x, /*use_h=*/0, ei, et);
    combine_kernel<CHID, true><<<dim3(MT, CHID / 64), 256>>>(x, W1_root, W1_rel, b1, nullptr);

    // Layer 2
    zero_agg_kernel<<<ZERO_BLOCKS, 256>>>();
    scatter_kernel<<<NE / 8, 256>>>(x, /*use_h=*/1, ei, et);
    combine_kernel<COUT, false><<<dim3(MT, COUT / 64), 256>>>(nullptr, W2_root, W2_rel, b2, out);

    normalize_kernel<<<(NN * 32 + 255) / 256, 256>>>(out);
}